// round 1
// baseline (speedup 1.0000x reference)
#include <cuda_runtime.h>
#include <cstdint>
#include <cstddef>

#define NN 20000
#define EE 320000
#define TT 24
#define HID 128
#define EPRIME (EE + NN)          // 340000 (edges + self loops)
#define TNT (TT * NN)             // 480000 batched rows

// ---------------- static scratch (no runtime allocation allowed) ----------------
__device__ float g_h[(size_t)TNT * HID];        // node features, all timesteps (in-place across GAT layers)
__device__ float g_xp[(size_t)TNT * HID];       // h @ W per layer
__device__ float g_asrc[(size_t)TNT * 4];
__device__ float g_adst[(size_t)TNT * 4];
__device__ float g_rinv[(size_t)TNT * 4];       // 1/denom per (t,node,head)
__device__ float g_alpha[(size_t)TT * EPRIME * 4]; // unnormalized exp weights per edge
__device__ int   g_deg[NN];
__device__ int   g_rowptr[NN + 1];
__device__ int   g_cursor[NN];
__device__ int   g_csrsrc[EPRIME];
__device__ float g_WihT0[HID * 512];
__device__ float g_WhhT0[HID * 512];
__device__ float g_Wcat1[2 * HID * 512];        // [Wih1^T ; Whh1^T]
__device__ float g_zx0[(size_t)TNT * 512];      // precomputed x@Wih0^T for all t
__device__ float g_zh[(size_t)NN * 512];
__device__ float g_z1[(size_t)NN * 512];
__device__ float g_hcat[(size_t)NN * 256];      // [h0 | h1] interleaved per node
__device__ float g_c0[(size_t)NN * HID];
__device__ float g_c1[(size_t)NN * HID];

// ---------------- helpers ----------------
__device__ __forceinline__ float wsum(float v) {
    #pragma unroll
    for (int o = 16; o; o >>= 1) v += __shfl_xor_sync(0xffffffffu, v, o);
    return v;
}
__device__ __forceinline__ float wmax(float v) {
    #pragma unroll
    for (int o = 16; o; o >>= 1) v = fmaxf(v, __shfl_xor_sync(0xffffffffu, v, o));
    return v;
}
__device__ __forceinline__ float lrelu(float x) { return x > 0.f ? x : 0.2f * x; }

// ---------------- CSR build ----------------
__global__ void hist_dst(const int* __restrict__ dst) {
    int e = blockIdx.x * blockDim.x + threadIdx.x;
    if (e < EE) atomicAdd(&g_deg[dst[e]], 1);
}

__global__ void scan_rowptr() {
    __shared__ int sums[1024];
    int tid = threadIdx.x;
    const int chunk = (NN + 1023) / 1024;
    int start = tid * chunk;
    int end = min(start + chunk, NN);
    int local = 0;
    for (int i = start; i < end; i++) local += g_deg[i] + 1; // +1 self loop
    sums[tid] = local;
    __syncthreads();
    for (int off = 1; off < 1024; off <<= 1) {
        int v = (tid >= off) ? sums[tid - off] : 0;
        __syncthreads();
        if (tid >= off) sums[tid] += v;
        __syncthreads();
    }
    int run = (tid == 0) ? 0 : sums[tid - 1];
    for (int i = start; i < end; i++) { g_rowptr[i] = run; run += g_deg[i] + 1; }
    if (start < NN && end == NN) g_rowptr[NN] = run;
}

__global__ void init_cursor_selfloop() {
    int n = blockIdx.x * blockDim.x + threadIdx.x;
    if (n < NN) {
        g_cursor[n] = g_rowptr[n];
        g_csrsrc[g_rowptr[n + 1] - 1] = n;   // self loop occupies last slot
    }
}

__global__ void scatter_edges(const int* __restrict__ src, const int* __restrict__ dst) {
    int e = blockIdx.x * blockDim.x + threadIdx.x;
    if (e < EE) {
        int p = atomicAdd(&g_cursor[dst[e]], 1);
        g_csrsrc[p] = src[e];
    }
}

// ---------------- weight transpose (512x128 -> 128x512) ----------------
__global__ void transp_512x128(const float* __restrict__ src, float* __restrict__ dst) {
    int idx = blockIdx.x * blockDim.x + threadIdx.x;
    if (idx < 512 * 128) {
        int r = idx / 128, k = idx % 128;
        dst[(size_t)k * 512 + r] = src[idx];
    }
}

// ---------------- input projection (batched over t) ----------------
__global__ void proj_kernel(const float* __restrict__ xs, const float* __restrict__ xd,
                            const float* __restrict__ W, const float* __restrict__ b) {
    int bn = blockIdx.x;                 // t*NN + n
    int t = bn / NN, n = bn - t * NN;
    __shared__ float f[24];
    int j = threadIdx.x;                 // 128
    if (j < 16) f[j] = xs[(size_t)n * 16 + j];
    else if (j < 24) f[j] = xd[((size_t)t * NN + n) * 8 + (j - 16)];
    __syncthreads();
    float acc = b[j];
    #pragma unroll
    for (int k = 0; k < 24; k++) acc = fmaf(f[k], W[k * HID + j], acc);
    g_h[(size_t)bn * HID + j] = acc;
}

// ---------------- generic fp32 GEMM: C[M,N] = A[M,K(lda)] @ B[K,N] ----------------
__global__ __launch_bounds__(256) void sgemm128(
    const float* __restrict__ A, int lda,
    const float* __restrict__ B,
    float* __restrict__ C,
    int M, int N, int K) {
    constexpr int BM = 128, BN = 128, BK = 8, TM = 8, TN = 8;
    __shared__ float As[BK][BM];
    __shared__ float Bs[BK][BN];
    int tid = threadIdx.x;
    int cRow = blockIdx.y, cCol = blockIdx.x;
    int tCol = tid % 16, tRow = tid / 16;
    int aRow = tid >> 1;
    int aCol = (tid & 1) * 4;
    int bRow = tid >> 5;
    int bCol = (tid & 31) * 4;
    size_t gARow = (size_t)cRow * BM + aRow;
    const float* Aptr = A + gARow * (size_t)lda;
    const float* Bptr = B + (size_t)cCol * BN;
    float acc[TM][TN];
    #pragma unroll
    for (int i = 0; i < TM; i++)
        #pragma unroll
        for (int j = 0; j < TN; j++) acc[i][j] = 0.f;

    for (int k0 = 0; k0 < K; k0 += BK) {
        float4 a4 = make_float4(0.f, 0.f, 0.f, 0.f);
        if (gARow < (size_t)M) a4 = *(const float4*)(Aptr + k0 + aCol);
        As[aCol + 0][aRow] = a4.x;
        As[aCol + 1][aRow] = a4.y;
        As[aCol + 2][aRow] = a4.z;
        As[aCol + 3][aRow] = a4.w;
        *(float4*)&Bs[bRow][bCol] = *(const float4*)(Bptr + (size_t)(k0 + bRow) * N + bCol);
        __syncthreads();
        #pragma unroll
        for (int kk = 0; kk < BK; kk++) {
            float regM[TM], regN[TN];
            #pragma unroll
            for (int i = 0; i < TM; i++) regM[i] = As[kk][tRow * TM + i];
            #pragma unroll
            for (int j = 0; j < TN; j++) regN[j] = Bs[kk][tCol * TN + j];
            #pragma unroll
            for (int i = 0; i < TM; i++)
                #pragma unroll
                for (int j = 0; j < TN; j++)
                    acc[i][j] = fmaf(regM[i], regN[j], acc[i][j]);
        }
        __syncthreads();
    }
    #pragma unroll
    for (int i = 0; i < TM; i++) {
        size_t row = (size_t)cRow * BM + tRow * TM + i;
        if (row < (size_t)M) {
            float* Cr = C + row * (size_t)N + cCol * BN + tCol * TN;
            *(float4*)(Cr) = make_float4(acc[i][0], acc[i][1], acc[i][2], acc[i][3]);
            *(float4*)(Cr + 4) = make_float4(acc[i][4], acc[i][5], acc[i][6], acc[i][7]);
        }
    }
}

// ---------------- GAT attention scores: a_src/a_dst per (t,node) ----------------
__global__ void attn_scores(const float* __restrict__ aS, const float* __restrict__ aD) {
    int gt = blockIdx.x * blockDim.x + threadIdx.x;
    int w = gt >> 5, lane = gt & 31;
    if (w >= TNT) return;
    const float* xr = g_xp + (size_t)w * HID;
    float s[4], d[4];
    #pragma unroll
    for (int h = 0; h < 4; h++) {
        float v = xr[h * 32 + lane];
        s[h] = v * aS[h * 32 + lane];
        d[h] = v * aD[h * 32 + lane];
    }
    #pragma unroll
    for (int h = 0; h < 4; h++) { s[h] = wsum(s[h]); d[h] = wsum(d[h]); }
    if (lane == 0) {
        *(float4*)&g_asrc[(size_t)w * 4] = make_float4(s[0], s[1], s[2], s[3]);
        *(float4*)&g_adst[(size_t)w * 4] = make_float4(d[0], d[1], d[2], d[3]);
    }
}

// ---------------- per-(t,node) segment softmax (warp per node) ----------------
__global__ void gat_softmax() {
    int gt = blockIdx.x * blockDim.x + threadIdx.x;
    int w = gt >> 5, lane = gt & 31;
    if (w >= TNT) return;
    int t = w / NN, n = w - t * NN;
    int rs = g_rowptr[n], re = g_rowptr[n + 1];
    float* ab = g_alpha + (size_t)t * EPRIME * 4;
    const float* asb = g_asrc + (size_t)t * NN * 4;
    float4 ad = *(const float4*)&g_adst[(size_t)w * 4];

    float m0 = -1e30f, m1 = -1e30f, m2 = -1e30f, m3 = -1e30f;
    for (int i = rs + lane; i < re; i += 32) {
        int s = g_csrsrc[i];
        float4 as = *(const float4*)&asb[(size_t)s * 4];
        float e0 = lrelu(as.x + ad.x);
        float e1 = lrelu(as.y + ad.y);
        float e2 = lrelu(as.z + ad.z);
        float e3 = lrelu(as.w + ad.w);
        *(float4*)&ab[(size_t)i * 4] = make_float4(e0, e1, e2, e3);
        m0 = fmaxf(m0, e0); m1 = fmaxf(m1, e1); m2 = fmaxf(m2, e2); m3 = fmaxf(m3, e3);
    }
    m0 = wmax(m0); m1 = wmax(m1); m2 = wmax(m2); m3 = wmax(m3);
    float s0 = 0.f, s1 = 0.f, s2 = 0.f, s3 = 0.f;
    for (int i = rs + lane; i < re; i += 32) {
        float4 e = *(const float4*)&ab[(size_t)i * 4];
        e.x = __expf(e.x - m0); e.y = __expf(e.y - m1);
        e.z = __expf(e.z - m2); e.w = __expf(e.w - m3);
        *(float4*)&ab[(size_t)i * 4] = e;
        s0 += e.x; s1 += e.y; s2 += e.z; s3 += e.w;
    }
    s0 = wsum(s0); s1 = wsum(s1); s2 = wsum(s2); s3 = wsum(s3);
    if (lane == 0)
        *(float4*)&g_rinv[(size_t)w * 4] = make_float4(
            1.f / (s0 + 1e-16f), 1.f / (s1 + 1e-16f),
            1.f / (s2 + 1e-16f), 1.f / (s3 + 1e-16f));
}

// ---------------- aggregate + bias + residual + LayerNorm + ReLU (in place on g_h) ----------------
__global__ void gat_aggregate(const float* __restrict__ gb, const float* __restrict__ lg,
                              const float* __restrict__ lb) {
    int gt = blockIdx.x * blockDim.x + threadIdx.x;
    int w = gt >> 5, lane = gt & 31;
    if (w >= TNT) return;
    int t = w / NN, n = w - t * NN;
    int rs = g_rowptr[n], re = g_rowptr[n + 1];
    const float* ab = g_alpha + (size_t)t * EPRIME * 4;
    const float* xb = g_xp + (size_t)t * NN * HID;

    float a0 = 0.f, a1 = 0.f, a2 = 0.f, a3 = 0.f;
    for (int i = rs; i < re; i++) {
        int s = g_csrsrc[i];                                  // warp-uniform broadcast
        float4 al = *(const float4*)&ab[(size_t)i * 4];       // broadcast
        const float* xr = xb + (size_t)s * HID;               // coalesced 128B per head
        a0 = fmaf(al.x, xr[lane], a0);
        a1 = fmaf(al.y, xr[32 + lane], a1);
        a2 = fmaf(al.z, xr[64 + lane], a2);
        a3 = fmaf(al.w, xr[96 + lane], a3);
    }
    float4 rv = *(const float4*)&g_rinv[(size_t)w * 4];
    float* hr = g_h + (size_t)w * HID;
    float o0 = a0 * rv.x + gb[lane]      + hr[lane];
    float o1 = a1 * rv.y + gb[32 + lane] + hr[32 + lane];
    float o2 = a2 * rv.z + gb[64 + lane] + hr[64 + lane];
    float o3 = a3 * rv.w + gb[96 + lane] + hr[96 + lane];
    float mu = wsum(o0 + o1 + o2 + o3) * (1.f / 128.f);
    float d0 = o0 - mu, d1 = o1 - mu, d2 = o2 - mu, d3 = o3 - mu;
    float var = wsum(d0 * d0 + d1 * d1 + d2 * d2 + d3 * d3) * (1.f / 128.f);
    float rstd = rsqrtf(var + 1e-5f);
    hr[lane]       = fmaxf(lg[lane]       * d0 * rstd + lb[lane],       0.f);
    hr[32 + lane]  = fmaxf(lg[32 + lane]  * d1 * rstd + lb[32 + lane],  0.f);
    hr[64 + lane]  = fmaxf(lg[64 + lane]  * d2 * rstd + lb[64 + lane],  0.f);
    hr[96 + lane]  = fmaxf(lg[96 + lane]  * d3 * rstd + lb[96 + lane],  0.f);
}

// ---------------- LSTM gates ----------------
__global__ void lstm_gates(const float* __restrict__ zx, const float* __restrict__ zh,
                           const float* __restrict__ bih, const float* __restrict__ bhh,
                           float* __restrict__ c, float* __restrict__ hout) {
    int idx = blockIdx.x * blockDim.x + threadIdx.x;
    if (idx >= NN * HID) return;
    int n = idx >> 7, j = idx & 127;
    const float* zr = zx + (size_t)n * 512;
    float zi = zr[j], zf = zr[128 + j], zg = zr[256 + j], zo = zr[384 + j];
    if (zh) {
        const float* hr2 = zh + (size_t)n * 512;
        zi += hr2[j]; zf += hr2[128 + j]; zg += hr2[256 + j]; zo += hr2[384 + j];
    }
    zi += bih[j]       + bhh[j];
    zf += bih[128 + j] + bhh[128 + j];
    zg += bih[256 + j] + bhh[256 + j];
    zo += bih[384 + j] + bhh[384 + j];
    float ig = 1.f / (1.f + __expf(-zi));
    float fg = 1.f / (1.f + __expf(-zf));
    float gg = tanhf(zg);
    float og = 1.f / (1.f + __expf(-zo));
    float cn = fg * c[idx] + ig * gg;
    c[idx] = cn;
    hout[(size_t)n * 256 + j] = og * tanhf(cn);   // into hcat (stride 256)
}

// ---------------- output head ----------------
__global__ void head_kernel(const float* __restrict__ W1, const float* __restrict__ b1,
                            const float* __restrict__ W2, const float* __restrict__ b2,
                            float* __restrict__ out) {
    __shared__ float hrow[128];
    __shared__ float part[2];
    int n = blockIdx.x;
    int j = threadIdx.x;  // 64
    const float* hr = g_hcat + (size_t)n * 256 + 128;   // h1
    hrow[j] = hr[j];
    hrow[j + 64] = hr[j + 64];
    __syncthreads();
    float acc = b1[j];
    #pragma unroll
    for (int k = 0; k < 128; k++) acc = fmaf(hrow[k], W1[k * 64 + j], acc);
    float v = fmaxf(acc, 0.f) * W2[j];
    v = wsum(v);
    if ((j & 31) == 0) part[j >> 5] = v;
    __syncthreads();
    if (j == 0) out[n] = part[0] + part[1] + b2[0];
}

// ---------------- host launch ----------------
static float* symf(const void* s) { void* p = nullptr; cudaGetSymbolAddress(&p, s); return (float*)p; }

extern "C" void kernel_launch(void* const* d_in, const int* in_sizes, int n_in,
                              void* d_out, int out_size) {
    const float* xs    = (const float*)d_in[0];
    const float* xd    = (const float*)d_in[1];
    const int*   ei    = (const int*)  d_in[2];
    const float* projW = (const float*)d_in[3];
    const float* projb = (const float*)d_in[4];
    const float* gatW  = (const float*)d_in[5];
    const float* attS  = (const float*)d_in[6];
    const float* attD  = (const float*)d_in[7];
    const float* gatb  = (const float*)d_in[8];
    const float* lng   = (const float*)d_in[9];
    const float* lnb   = (const float*)d_in[10];
    const float* Wih0  = (const float*)d_in[11];
    const float* Whh0  = (const float*)d_in[12];
    const float* bih0  = (const float*)d_in[13];
    const float* bhh0  = (const float*)d_in[14];
    const float* Wih1  = (const float*)d_in[15];
    const float* Whh1  = (const float*)d_in[16];
    const float* bih1  = (const float*)d_in[17];
    const float* bhh1  = (const float*)d_in[18];
    const float* oW1   = (const float*)d_in[19];
    const float* ob1   = (const float*)d_in[20];
    const float* oW2   = (const float*)d_in[21];
    const float* ob2   = (const float*)d_in[22];
    float* out = (float*)d_out;

    float* p_h     = symf(g_h);
    float* p_xp    = symf(g_xp);
    float* p_WihT0 = symf(g_WihT0);
    float* p_WhhT0 = symf(g_WhhT0);
    float* p_Wcat1 = symf(g_Wcat1);
    float* p_zx0   = symf(g_zx0);
    float* p_zh    = symf(g_zh);
    float* p_z1    = symf(g_z1);
    float* p_hcat  = symf(g_hcat);
    float* p_c0    = symf(g_c0);
    float* p_c1    = symf(g_c1);
    float* p_deg   = symf(g_deg);

    // --- CSR build (once per launch, same edges across all t/layers) ---
    cudaMemsetAsync(p_deg, 0, NN * sizeof(int));
    hist_dst<<<(EE + 255) / 256, 256>>>(ei + EE);
    scan_rowptr<<<1, 1024>>>();
    init_cursor_selfloop<<<(NN + 255) / 256, 256>>>();
    scatter_edges<<<(EE + 255) / 256, 256>>>(ei, ei + EE);

    // --- LSTM weight transposes ---
    const int TB = (512 * 128 + 255) / 256;
    transp_512x128<<<TB, 256>>>(Wih0, p_WihT0);
    transp_512x128<<<TB, 256>>>(Whh0, p_WhhT0);
    transp_512x128<<<TB, 256>>>(Wih1, p_Wcat1);
    transp_512x128<<<TB, 256>>>(Whh1, p_Wcat1 + 128 * 512);

    // --- zero LSTM state ---
    cudaMemsetAsync(p_hcat, 0, (size_t)NN * 256 * sizeof(float));
    cudaMemsetAsync(p_c0,   0, (size_t)NN * HID * sizeof(float));
    cudaMemsetAsync(p_c1,   0, (size_t)NN * HID * sizeof(float));

    // --- GNN phase, batched over all T timesteps ---
    proj_kernel<<<TNT, 128>>>(xs, xd, projW, projb);

    const int WBLK = (TNT * 32 + 255) / 256;   // warp-per-(t,node) kernels
    for (int l = 0; l < 3; l++) {
        sgemm128<<<dim3(1, (TNT + 127) / 128), 256>>>(p_h, HID, gatW + (size_t)l * HID * HID,
                                                      p_xp, TNT, HID, HID);
        attn_scores<<<WBLK, 256>>>(attS + l * 128, attD + l * 128);
        gat_softmax<<<WBLK, 256>>>();
        gat_aggregate<<<WBLK, 256>>>(gatb + l * 128, lng + l * 128, lnb + l * 128);
    }

    // --- precompute x@Wih0^T for all timesteps in one big GEMM ---
    sgemm128<<<dim3(4, (TNT + 127) / 128), 256>>>(p_h, HID, p_WihT0, p_zx0, TNT, 512, HID);

    // --- sequential LSTM over T ---
    const dim3 gemmNN(4, (NN + 127) / 128);
    const int GBLK = (NN * HID + 255) / 256;
    for (int t = 0; t < TT; t++) {
        // layer 0: z0 = zx0[t] + h0@Whh0^T
        sgemm128<<<gemmNN, 256>>>(p_hcat, 256, p_WhhT0, p_zh, NN, 512, HID);
        lstm_gates<<<GBLK, 256>>>(p_zx0 + (size_t)t * NN * 512, p_zh, bih0, bhh0, p_c0, p_hcat);
        // layer 1: z1 = [h0|h1] @ [Wih1^T;Whh1^T]
        sgemm128<<<gemmNN, 256>>>(p_hcat, 256, p_Wcat1, p_z1, NN, 512, 256);
        lstm_gates<<<GBLK, 256>>>(p_z1, nullptr, bih1, bhh1, p_c1, p_hcat + 128);
    }

    // --- output head ---
    head_kernel<<<NN, 64>>>(oW1, ob1, oW2, ob2, out);
}

// round 11
// speedup vs baseline: 1.2594x; 1.2594x over previous
#include <cuda_runtime.h>
#include <mma.h>
#include <cstdint>
#include <cstddef>

using namespace nvcuda;

#define NN 20000
#define NNP 20096                 // padded to multiple of 128
#define EE 320000
#define TT 24
#define HID 128
#define EPRIME (EE + NN)          // 340000 (edges + self loops)
#define TNT (TT * NN)             // 480000 batched rows (multiple of 128)

// ---------------- static scratch (no runtime allocation allowed) ----------------
__device__ float g_h[(size_t)TNT * HID];        // node features, all timesteps
__device__ float g_xp[(size_t)TNT * HID];       // h @ W per layer
__device__ float g_asrc[(size_t)TNT * 4];
__device__ float g_adst[(size_t)TNT * 4];
__device__ float g_rinv[(size_t)TNT * 4];
__device__ float g_alpha[(size_t)TT * EPRIME * 4];
__device__ int   g_deg[NN];
__device__ int   g_rowptr[NN + 1];
__device__ int   g_cursor[NN];
__device__ int   g_csrsrc[EPRIME];
__device__ float g_WihT0[HID * 512];
__device__ float g_WhhT0[HID * 512];
__device__ float g_Wcat1[2 * HID * 512];        // [Wih1^T ; Whh1^T] as [256 K, 512 N]
__device__ float g_zx0[(size_t)TNT * 512];      // precomputed x@Wih0^T for all t
__device__ float g_zh[(size_t)NNP * 512];
__device__ float g_z1[(size_t)NNP * 512];
__device__ float g_hcat[(size_t)NNP * 256];     // [h0 | h1] per node, pad rows stay 0
__device__ float g_c0[(size_t)NN * HID];
__device__ float g_c1[(size_t)NN * HID];

// ---------------- helpers ----------------
__device__ __forceinline__ float wsum(float v) {
    #pragma unroll
    for (int o = 16; o; o >>= 1) v += __shfl_xor_sync(0xffffffffu, v, o);
    return v;
}
__device__ __forceinline__ float wmax(float v) {
    #pragma unroll
    for (int o = 16; o; o >>= 1) v = fmaxf(v, __shfl_xor_sync(0xffffffffu, v, o));
    return v;
}
__device__ __forceinline__ float lrelu(float x) { return x > 0.f ? x : 0.2f * x; }

// ---------------- CSR build ----------------
__global__ void hist_dst(const int* __restrict__ dst) {
    int e = blockIdx.x * blockDim.x + threadIdx.x;
    if (e < EE) atomicAdd(&g_deg[dst[e]], 1);
}

__global__ void scan_rowptr() {
    __shared__ int sums[1024];
    int tid = threadIdx.x;
    const int chunk = (NN + 1023) / 1024;
    int start = tid * chunk;
    int end = min(start + chunk, NN);
    int local = 0;
    for (int i = start; i < end; i++) local += g_deg[i] + 1; // +1 self loop
    sums[tid] = local;
    __syncthreads();
    for (int off = 1; off < 1024; off <<= 1) {
        int v = (tid >= off) ? sums[tid - off] : 0;
        __syncthreads();
        if (tid >= off) sums[tid] += v;
        __syncthreads();
    }
    int run = (tid == 0) ? 0 : sums[tid - 1];
    for (int i = start; i < end; i++) { g_rowptr[i] = run; run += g_deg[i] + 1; }
    if (start < NN && end == NN) g_rowptr[NN] = run;
}

__global__ void init_cursor_selfloop() {
    int n = blockIdx.x * blockDim.x + threadIdx.x;
    if (n < NN) {
        g_cursor[n] = g_rowptr[n];
        g_csrsrc[g_rowptr[n + 1] - 1] = n;
    }
}

__global__ void scatter_edges(const int* __restrict__ src, const int* __restrict__ dst) {
    int e = blockIdx.x * blockDim.x + threadIdx.x;
    if (e < EE) {
        int p = atomicAdd(&g_cursor[dst[e]], 1);
        g_csrsrc[p] = src[e];
    }
}

// ---------------- weight transpose (512x128 -> 128x512) ----------------
__global__ void transp_512x128(const float* __restrict__ src, float* __restrict__ dst) {
    int idx = blockIdx.x * blockDim.x + threadIdx.x;
    if (idx < 512 * 128) {
        int r = idx / 128, k = idx % 128;
        dst[(size_t)k * 512 + r] = src[idx];
    }
}
// transpose Wih1/Whh1 [512,128] into Wcat1 [256,512]: rows 0..127 = Wih1^T, 128..255 = Whh1^T
__global__ void build_wcat1(const float* __restrict__ Wih1, const float* __restrict__ Whh1) {
    int idx = blockIdx.x * blockDim.x + threadIdx.x;
    if (idx < 512 * 128) {
        int r = idx / 128, k = idx % 128;
        g_Wcat1[(size_t)k * 512 + r]         = Wih1[idx];
        g_Wcat1[(size_t)(k + 128) * 512 + r] = Whh1[idx];
    }
}

// ---------------- input projection (batched over t) ----------------
__global__ void proj_kernel(const float* __restrict__ xs, const float* __restrict__ xd,
                            const float* __restrict__ W, const float* __restrict__ b) {
    int bn = blockIdx.x;                 // t*NN + n
    int t = bn / NN, n = bn - t * NN;
    __shared__ float f[24];
    int j = threadIdx.x;                 // 128
    if (j < 16) f[j] = xs[(size_t)n * 16 + j];
    else if (j < 24) f[j] = xd[((size_t)t * NN + n) * 8 + (j - 16)];
    __syncthreads();
    float acc = b[j];
    #pragma unroll
    for (int k = 0; k < 24; k++) acc = fmaf(f[k], W[k * HID + j], acc);
    g_h[(size_t)bn * HID + j] = acc;
}

// ---------------- tf32 tensor-core GEMM: C[M,N] = A[M,K(lda)] @ B[K,N] ----------------
// M must be a multiple of 128; N multiple of 128; K multiple of 32.
// Block: 128x128 tile, 256 threads (8 warps as 2x4), warp tile 64x32 = 4x2 wmma 16x16x8.
__global__ __launch_bounds__(256) void sgemm_tc(
    const float* __restrict__ A, int lda,
    const float* __restrict__ B,
    float* __restrict__ C,
    int N, int K) {
    constexpr int BK = 32;
    __shared__ float As[128][BK + 8];    // ldm 40
    __shared__ float Bs[BK][128 + 8];    // ldm 136

    int tid = threadIdx.x;
    int warpId = tid >> 5;
    int wr = warpId >> 2;                // 0..1
    int wc = warpId & 3;                 // 0..3
    size_t rowBase = (size_t)blockIdx.y * 128;
    int colBase = blockIdx.x * 128;

    wmma::fragment<wmma::accumulator, 16, 16, 8, float> acc[4][2];
    #pragma unroll
    for (int i = 0; i < 4; i++)
        #pragma unroll
        for (int j = 0; j < 2; j++) wmma::fill_fragment(acc[i][j], 0.0f);

    for (int k0 = 0; k0 < K; k0 += BK) {
        // load A tile: 128 x 32 = 1024 float4, 256 threads x 4
        #pragma unroll
        for (int it = 0; it < 4; it++) {
            int i = tid + 256 * it;
            int r = i >> 3;              // 8 float4 per row
            int c = (i & 7) * 4;
            float4 v = *(const float4*)(A + (rowBase + r) * (size_t)lda + k0 + c);
            As[r][c] = v.x; As[r][c + 1] = v.y; As[r][c + 2] = v.z; As[r][c + 3] = v.w;
        }
        // load B tile: 32 x 128 = 1024 float4
        #pragma unroll
        for (int it = 0; it < 4; it++) {
            int i = tid + 256 * it;
            int r = i >> 5;              // 32 float4 per row
            int c = (i & 31) * 4;
            float4 v = *(const float4*)(B + (size_t)(k0 + r) * N + colBase + c);
            *(float4*)&Bs[r][c] = v;
        }
        __syncthreads();

        #pragma unroll
        for (int kk = 0; kk < BK; kk += 8) {
            wmma::fragment<wmma::matrix_a, 16, 16, 8, wmma::precision::tf32, wmma::row_major> af[4];
            wmma::fragment<wmma::matrix_b, 16, 16, 8, wmma::precision::tf32, wmma::row_major> bf[2];
            #pragma unroll
            for (int i = 0; i < 4; i++) {
                wmma::load_matrix_sync(af[i], &As[wr * 64 + i * 16][kk], BK + 8);
                #pragma unroll
                for (int e = 0; e < af[i].num_elements; e++)
                    af[i].x[e] = wmma::__float_to_tf32(af[i].x[e]);
            }
            #pragma unroll
            for (int j = 0; j < 2; j++) {
                wmma::load_matrix_sync(bf[j], &Bs[kk][wc * 32 + j * 16], 128 + 8);
                #pragma unroll
                for (int e = 0; e < bf[j].num_elements; e++)
                    bf[j].x[e] = wmma::__float_to_tf32(bf[j].x[e]);
            }
            #pragma unroll
            for (int i = 0; i < 4; i++)
                #pragma unroll
                for (int j = 0; j < 2; j++)
                    wmma::mma_sync(acc[i][j], af[i], bf[j], acc[i][j]);
        }
        __syncthreads();
    }

    #pragma unroll
    for (int i = 0; i < 4; i++)
        #pragma unroll
        for (int j = 0; j < 2; j++) {
            float* Cp = C + (rowBase + wr * 64 + i * 16) * (size_t)N + colBase + wc * 32 + j * 16;
            wmma::store_matrix_sync(Cp, acc[i][j], N, wmma::mem_row_major);
        }
}

// ---------------- GAT attention scores ----------------
__global__ void attn_scores(const float* __restrict__ aS, const float* __restrict__ aD) {
    int gt = blockIdx.x * blockDim.x + threadIdx.x;
    int w = gt >> 5, lane = gt & 31;
    if (w >= TNT) return;
    const float* xr = g_xp + (size_t)w * HID;
    float s[4], d[4];
    #pragma unroll
    for (int h = 0; h < 4; h++) {
        float v = xr[h * 32 + lane];
        s[h] = v * aS[h * 32 + lane];
        d[h] = v * aD[h * 32 + lane];
    }
    #pragma unroll
    for (int h = 0; h < 4; h++) { s[h] = wsum(s[h]); d[h] = wsum(d[h]); }
    if (lane == 0) {
        *(float4*)&g_asrc[(size_t)w * 4] = make_float4(s[0], s[1], s[2], s[3]);
        *(float4*)&g_adst[(size_t)w * 4] = make_float4(d[0], d[1], d[2], d[3]);
    }
}

// ---------------- per-(t,node) segment softmax (warp per node) ----------------
__global__ void gat_softmax() {
    int gt = blockIdx.x * blockDim.x + threadIdx.x;
    int w = gt >> 5, lane = gt & 31;
    if (w >= TNT) return;
    int t = w / NN, n = w - t * NN;
    int rs = g_rowptr[n], re = g_rowptr[n + 1];
    float* ab = g_alpha + (size_t)t * EPRIME * 4;
    const float* asb = g_asrc + (size_t)t * NN * 4;
    float4 ad = *(const float4*)&g_adst[(size_t)w * 4];

    float m0 = -1e30f, m1 = -1e30f, m2 = -1e30f, m3 = -1e30f;
    for (int i = rs + lane; i < re; i += 32) {
        int s = g_csrsrc[i];
        float4 as = *(const float4*)&asb[(size_t)s * 4];
        float e0 = lrelu(as.x + ad.x);
        float e1 = lrelu(as.y + ad.y);
        float e2 = lrelu(as.z + ad.z);
        float e3 = lrelu(as.w + ad.w);
        *(float4*)&ab[(size_t)i * 4] = make_float4(e0, e1, e2, e3);
        m0 = fmaxf(m0, e0); m1 = fmaxf(m1, e1); m2 = fmaxf(m2, e2); m3 = fmaxf(m3, e3);
    }
    m0 = wmax(m0); m1 = wmax(m1); m2 = wmax(m2); m3 = wmax(m3);
    float s0 = 0.f, s1 = 0.f, s2 = 0.f, s3 = 0.f;
    for (int i = rs + lane; i < re; i += 32) {
        float4 e = *(const float4*)&ab[(size_t)i * 4];
        e.x = __expf(e.x - m0); e.y = __expf(e.y - m1);
        e.z = __expf(e.z - m2); e.w = __expf(e.w - m3);
        *(float4*)&ab[(size_t)i * 4] = e;
        s0 += e.x; s1 += e.y; s2 += e.z; s3 += e.w;
    }
    s0 = wsum(s0); s1 = wsum(s1); s2 = wsum(s2); s3 = wsum(s3);
    if (lane == 0)
        *(float4*)&g_rinv[(size_t)w * 4] = make_float4(
            1.f / (s0 + 1e-16f), 1.f / (s1 + 1e-16f),
            1.f / (s2 + 1e-16f), 1.f / (s3 + 1e-16f));
}

// ---------------- aggregate + bias + residual + LayerNorm + ReLU ----------------
__global__ void gat_aggregate(const float* __restrict__ gb, const float* __restrict__ lg,
                              const float* __restrict__ lb) {
    int gt = blockIdx.x * blockDim.x + threadIdx.x;
    int w = gt >> 5, lane = gt & 31;
    if (w >= TNT) return;
    int t = w / NN, n = w - t * NN;
    int rs = g_rowptr[n], re = g_rowptr[n + 1];
    const float* ab = g_alpha + (size_t)t * EPRIME * 4;
    const float* xb = g_xp + (size_t)t * NN * HID;

    float a0 = 0.f, a1 = 0.f, a2 = 0.f, a3 = 0.f;
    for (int i = rs; i < re; i++) {
        int s = g_csrsrc[i];
        float4 al = *(const float4*)&ab[(size_t)i * 4];
        const float* xr = xb + (size_t)s * HID;
        a0 = fmaf(al.x, xr[lane], a0);
        a1 = fmaf(al.y, xr[32 + lane], a1);
        a2 = fmaf(al.z, xr[64 + lane], a2);
        a3 = fmaf(al.w, xr[96 + lane], a3);
    }
    float4 rv = *(const float4*)&g_rinv[(size_t)w * 4];
    float* hr = g_h + (size_t)w * HID;
    float o0 = a0 * rv.x + gb[lane]      + hr[lane];
    float o1 = a1 * rv.y + gb[32 + lane] + hr[32 + lane];
    float o2 = a2 * rv.z + gb[64 + lane] + hr[64 + lane];
    float o3 = a3 * rv.w + gb[96 + lane] + hr[96 + lane];
    float mu = wsum(o0 + o1 + o2 + o3) * (1.f / 128.f);
    float d0 = o0 - mu, d1 = o1 - mu, d2 = o2 - mu, d3 = o3 - mu;
    float var = wsum(d0 * d0 + d1 * d1 + d2 * d2 + d3 * d3) * (1.f / 128.f);
    float rstd = rsqrtf(var + 1e-5f);
    hr[lane]       = fmaxf(lg[lane]       * d0 * rstd + lb[lane],       0.f);
    hr[32 + lane]  = fmaxf(lg[32 + lane]  * d1 * rstd + lb[32 + lane],  0.f);
    hr[64 + lane]  = fmaxf(lg[64 + lane]  * d2 * rstd + lb[64 + lane],  0.f);
    hr[96 + lane]  = fmaxf(lg[96 + lane]  * d3 * rstd + lb[96 + lane],  0.f);
}

// ---------------- LSTM gates ----------------
__global__ void lstm_gates(const float* __restrict__ zx, const float* __restrict__ zh,
                           const float* __restrict__ bih, const float* __restrict__ bhh,
                           float* __restrict__ c, float* __restrict__ hout) {
    int idx = blockIdx.x * blockDim.x + threadIdx.x;
    if (idx >= NN * HID) return;
    int n = idx >> 7, j = idx & 127;
    const float* zr = zx + (size_t)n * 512;
    float zi = zr[j], zf = zr[128 + j], zg = zr[256 + j], zo = zr[384 + j];
    if (zh) {
        const float* hr2 = zh + (size_t)n * 512;
        zi += hr2[j]; zf += hr2[128 + j]; zg += hr2[256 + j]; zo += hr2[384 + j];
    }
    zi += bih[j]       + bhh[j];
    zf += bih[128 + j] + bhh[128 + j];
    zg += bih[256 + j] + bhh[256 + j];
    zo += bih[384 + j] + bhh[384 + j];
    float ig = 1.f / (1.f + __expf(-zi));
    float fg = 1.f / (1.f + __expf(-zf));
    float gg = tanhf(zg);
    float og = 1.f / (1.f + __expf(-zo));
    float cn = fg * c[idx] + ig * gg;
    c[idx] = cn;
    hout[(size_t)n * 256 + j] = og * tanhf(cn);
}

// ---------------- output head ----------------
__global__ void head_kernel(const float* __restrict__ W1, const float* __restrict__ b1,
                            const float* __restrict__ W2, const float* __restrict__ b2,
                            float* __restrict__ out) {
    __shared__ float hrow[128];
    __shared__ float part[2];
    int n = blockIdx.x;
    int j = threadIdx.x;  // 64
    const float* hr = g_hcat + (size_t)n * 256 + 128;   // h1
    hrow[j] = hr[j];
    hrow[j + 64] = hr[j + 64];
    __syncthreads();
    float acc = b1[j];
    #pragma unroll
    for (int k = 0; k < 128; k++) acc = fmaf(hrow[k], W1[k * 64 + j], acc);
    float v = fmaxf(acc, 0.f) * W2[j];
    v = wsum(v);
    if ((j & 31) == 0) part[j >> 5] = v;
    __syncthreads();
    if (j == 0) out[n] = part[0] + part[1] + b2[0];
}

// ---------------- host launch ----------------
static float* symf(const void* s) { void* p = nullptr; cudaGetSymbolAddress(&p, s); return (float*)p; }

extern "C" void kernel_launch(void* const* d_in, const int* in_sizes, int n_in,
                              void* d_out, int out_size) {
    const float* xs    = (const float*)d_in[0];
    const float* xd    = (const float*)d_in[1];
    const int*   ei    = (const int*)  d_in[2];
    const float* projW = (const float*)d_in[3];
    const float* projb = (const float*)d_in[4];
    const float* gatW  = (const float*)d_in[5];
    const float* attS  = (const float*)d_in[6];
    const float* attD  = (const float*)d_in[7];
    const float* gatb  = (const float*)d_in[8];
    const float* lng   = (const float*)d_in[9];
    const float* lnb   = (const float*)d_in[10];
    const float* Wih0  = (const float*)d_in[11];
    const float* Whh0  = (const float*)d_in[12];
    const float* bih0  = (const float*)d_in[13];
    const float* bhh0  = (const float*)d_in[14];
    const float* Wih1  = (const float*)d_in[15];
    const float* Whh1  = (const float*)d_in[16];
    const float* bih1  = (const float*)d_in[17];
    const float* bhh1  = (const float*)d_in[18];
    const float* oW1   = (const float*)d_in[19];
    const float* ob1   = (const float*)d_in[20];
    const float* oW2   = (const float*)d_in[21];
    const float* ob2   = (const float*)d_in[22];
    float* out = (float*)d_out;

    float* p_h     = symf(g_h);
    float* p_xp    = symf(g_xp);
    float* p_WihT0 = symf(g_WihT0);
    float* p_WhhT0 = symf(g_WhhT0);
    float* p_zx0   = symf(g_zx0);
    float* p_zh    = symf(g_zh);
    float* p_z1    = symf(g_z1);
    float* p_hcat  = symf(g_hcat);
    float* p_c0    = symf(g_c0);
    float* p_c1    = symf(g_c1);
    float* p_deg   = symf(g_deg);
    float* p_Wcat1 = symf(g_Wcat1);

    // --- CSR build ---
    cudaMemsetAsync(p_deg, 0, NN * sizeof(int));
    hist_dst<<<(EE + 255) / 256, 256>>>(ei + EE);
    scan_rowptr<<<1, 1024>>>();
    init_cursor_selfloop<<<(NN + 255) / 256, 256>>>();
    scatter_edges<<<(EE + 255) / 256, 256>>>(ei, ei + EE);

    // --- LSTM weight prep: keep [K,N] row-major for matrix_b ---
    const int TB = (512 * 128 + 255) / 256;
    transp_512x128<<<TB, 256>>>(Wih0, p_WihT0);
    transp_512x128<<<TB, 256>>>(Whh0, p_WhhT0);
    build_wcat1<<<TB, 256>>>(Wih1, Whh1);

    // --- zero LSTM state (hcat pad rows must stay 0 for padded GEMM rows) ---
    cudaMemsetAsync(p_hcat, 0, (size_t)NNP * 256 * sizeof(float));
    cudaMemsetAsync(p_c0,   0, (size_t)NN * HID * sizeof(float));
    cudaMemsetAsync(p_c1,   0, (size_t)NN * HID * sizeof(float));

    // --- GNN phase, batched over all T timesteps ---
    proj_kernel<<<TNT, 128>>>(xs, xd, projW, projb);

    const int WBLK = (TNT * 32 + 255) / 256;
    for (int l = 0; l < 3; l++) {
        sgemm_tc<<<dim3(1, TNT / 128), 256>>>(p_h, HID, gatW + (size_t)l * HID * HID,
                                              p_xp, HID, HID);
        attn_scores<<<WBLK, 256>>>(attS + l * 128, attD + l * 128);
        gat_softmax<<<WBLK, 256>>>();
        gat_aggregate<<<WBLK, 256>>>(gatb + l * 128, lng + l * 128, lnb + l * 128);
    }

    // --- precompute x@Wih0^T for all timesteps in one big GEMM ---
    sgemm_tc<<<dim3(4, TNT / 128), 256>>>(p_h, HID, p_WihT0, p_zx0, 512, HID);

    // --- sequential LSTM over T ---
    const dim3 gemmNN(4, NNP / 128);
    const int GBLK = (NN * HID + 255) / 256;
    for (int t = 0; t < TT; t++) {
        sgemm_tc<<<gemmNN, 256>>>(p_hcat, 256, p_WhhT0, p_zh, 512, HID);
        lstm_gates<<<GBLK, 256>>>(p_zx0 + (size_t)t * NN * 512, p_zh, bih0, bhh0, p_c0, p_hcat);
        sgemm_tc<<<gemmNN, 256>>>(p_hcat, 256, p_Wcat1, p_z1, 512, 256);
        lstm_gates<<<GBLK, 256>>>(p_z1, nullptr, bih1, bhh1, p_c1, p_hcat + 128);
    }

    // --- output head ---
    head_kernel<<<NN, 64>>>(oW1, ob1, oW2, ob2, out);
}

// round 14
// speedup vs baseline: 1.3609x; 1.0806x over previous
#include <cuda_runtime.h>
#include <mma.h>
#include <cstdint>
#include <cstddef>

using namespace nvcuda;

#define NN 20000
#define NNP 20096                 // padded to multiple of 128
#define EE 320000
#define TT 24
#define HID 128
#define EPRIME (EE + NN)          // 340000 (edges + self loops)
#define TNT (TT * NN)             // 480000 batched rows (multiple of 128)

// ---------------- static scratch (no runtime allocation allowed) ----------------
__device__ float g_h[(size_t)TNT * HID];        // node features, all timesteps
__device__ float g_xp[(size_t)TNT * HID];       // h @ W per layer
__device__ float g_asrc[(size_t)TNT * 4];
__device__ float g_adst[(size_t)TNT * 4];
__device__ float g_rinv[(size_t)TNT * 4];
__device__ float g_alpha[(size_t)TT * EPRIME * 4];
__device__ int   g_deg[NN];
__device__ int   g_rowptr[NN + 1];
__device__ int   g_cursor[NN];
__device__ int   g_csrsrc[EPRIME];
__device__ float g_WihT0[HID * 512];
__device__ float g_WhhT0[HID * 512];
__device__ float g_Wcat1[2 * HID * 512];        // [Wih1^T ; Whh1^T] as [256 K, 512 N]
__device__ float g_zx0[(size_t)TNT * 512];      // precomputed x@Wih0^T for all t
__device__ float g_zh[(size_t)NNP * 512];
__device__ float g_z1[(size_t)NNP * 512];
__device__ float g_hcat[(size_t)NNP * 256];     // [h0 | h1] per node, pad rows stay 0
__device__ float g_c0[(size_t)NN * HID];
__device__ float g_c1[(size_t)NN * HID];

// ---------------- helpers ----------------
__device__ __forceinline__ float wsum(float v) {
    #pragma unroll
    for (int o = 16; o; o >>= 1) v += __shfl_xor_sync(0xffffffffu, v, o);
    return v;
}
__device__ __forceinline__ float wmax(float v) {
    #pragma unroll
    for (int o = 16; o; o >>= 1) v = fmaxf(v, __shfl_xor_sync(0xffffffffu, v, o));
    return v;
}
__device__ __forceinline__ float lrelu(float x) { return x > 0.f ? x : 0.2f * x; }

__device__ __forceinline__ void cp_async16(void* smem_ptr, const void* gptr) {
    uint32_t sa = (uint32_t)__cvta_generic_to_shared(smem_ptr);
    asm volatile("cp.async.cg.shared.global [%0], [%1], 16;" :: "r"(sa), "l"(gptr));
}
__device__ __forceinline__ void cp_commit() { asm volatile("cp.async.commit_group;"); }
template<int W> __device__ __forceinline__ void cp_wait() {
    asm volatile("cp.async.wait_group %0;" :: "n"(W));
}

// ---------------- CSR build ----------------
__global__ void hist_dst(const int* __restrict__ dst) {
    int e = blockIdx.x * blockDim.x + threadIdx.x;
    if (e < EE) atomicAdd(&g_deg[dst[e]], 1);
}

__global__ void scan_rowptr() {
    __shared__ int sums[1024];
    int tid = threadIdx.x;
    const int chunk = (NN + 1023) / 1024;
    int start = tid * chunk;
    int end = min(start + chunk, NN);
    int local = 0;
    for (int i = start; i < end; i++) local += g_deg[i] + 1; // +1 self loop
    sums[tid] = local;
    __syncthreads();
    for (int off = 1; off < 1024; off <<= 1) {
        int v = (tid >= off) ? sums[tid - off] : 0;
        __syncthreads();
        if (tid >= off) sums[tid] += v;
        __syncthreads();
    }
    int run = (tid == 0) ? 0 : sums[tid - 1];
    for (int i = start; i < end; i++) { g_rowptr[i] = run; run += g_deg[i] + 1; }
    if (start < NN && end == NN) g_rowptr[NN] = run;
}

__global__ void init_cursor_selfloop() {
    int n = blockIdx.x * blockDim.x + threadIdx.x;
    if (n < NN) {
        g_cursor[n] = g_rowptr[n];
        g_csrsrc[g_rowptr[n + 1] - 1] = n;
    }
}

__global__ void scatter_edges(const int* __restrict__ src, const int* __restrict__ dst) {
    int e = blockIdx.x * blockDim.x + threadIdx.x;
    if (e < EE) {
        int p = atomicAdd(&g_cursor[dst[e]], 1);
        g_csrsrc[p] = src[e];
    }
}

// ---------------- weight transpose (512x128 -> 128x512) ----------------
__global__ void transp_512x128(const float* __restrict__ src, float* __restrict__ dst) {
    int idx = blockIdx.x * blockDim.x + threadIdx.x;
    if (idx < 512 * 128) {
        int r = idx / 128, k = idx % 128;
        dst[(size_t)k * 512 + r] = src[idx];
    }
}
// transpose Wih1/Whh1 [512,128] into Wcat1 [256,512]: rows 0..127 = Wih1^T, 128..255 = Whh1^T
__global__ void build_wcat1(const float* __restrict__ Wih1, const float* __restrict__ Whh1) {
    int idx = blockIdx.x * blockDim.x + threadIdx.x;
    if (idx < 512 * 128) {
        int r = idx / 128, k = idx % 128;
        g_Wcat1[(size_t)k * 512 + r]         = Wih1[idx];
        g_Wcat1[(size_t)(k + 128) * 512 + r] = Whh1[idx];
    }
}

// ---------------- input projection (batched over t) ----------------
__global__ void proj_kernel(const float* __restrict__ xs, const float* __restrict__ xd,
                            const float* __restrict__ W, const float* __restrict__ b) {
    int bn = blockIdx.x;                 // t*NN + n
    int t = bn / NN, n = bn - t * NN;
    __shared__ float f[24];
    int j = threadIdx.x;                 // 128
    if (j < 16) f[j] = xs[(size_t)n * 16 + j];
    else if (j < 24) f[j] = xd[((size_t)t * NN + n) * 8 + (j - 16)];
    __syncthreads();
    float acc = b[j];
    #pragma unroll
    for (int k = 0; k < 24; k++) acc = fmaf(f[k], W[k * HID + j], acc);
    g_h[(size_t)bn * HID + j] = acc;
}

// ---------------- tf32 tensor-core GEMM with cp.async double buffering ----------------
// C[M,N] = A[M,K(lda)] @ B[K,N]. M multiple of 128; N multiple of 128; K multiple of 32.
// Block: 128x128 tile, 256 threads (8 warps as 2x4), warp tile 64x32 = 4x2 wmma 16x16x8.
#define AS_LD 40
#define BS_LD 136
#define A_BUF (128 * AS_LD)
#define B_BUF (32 * BS_LD)
#define GEMM_SMEM_BYTES ((2 * A_BUF + 2 * B_BUF) * 4)

__global__ __launch_bounds__(256) void sgemm_tc(
    const float* __restrict__ A, int lda,
    const float* __restrict__ B,
    float* __restrict__ C,
    int N, int K) {
    constexpr int BK = 32;
    extern __shared__ float sm[];
    float* Asm = sm;                       // [2][128][AS_LD]
    float* Bsm = sm + 2 * A_BUF;           // [2][32][BS_LD]

    int tid = threadIdx.x;
    int warpId = tid >> 5;
    int wr = warpId >> 2;                // 0..1
    int wc = warpId & 3;                 // 0..3
    size_t rowBase = (size_t)blockIdx.y * 128;
    int colBase = blockIdx.x * 128;

    // per-thread tile-load coordinates (4 float4 each for A and B)
    int arr[4], arc[4], brr[4], brc[4];
    #pragma unroll
    for (int it = 0; it < 4; it++) {
        int i = tid + 256 * it;
        arr[it] = i >> 3;                // A: 8 float4 per 32-float row
        arc[it] = (i & 7) * 4;
        brr[it] = i >> 5;                // B: 32 float4 per 128-float row
        brc[it] = (i & 31) * 4;
    }

    wmma::fragment<wmma::accumulator, 16, 16, 8, float> acc[4][2];
    #pragma unroll
    for (int i = 0; i < 4; i++)
        #pragma unroll
        for (int j = 0; j < 2; j++) wmma::fill_fragment(acc[i][j], 0.0f);

    const int nk = K / BK;

    // prologue: stage 0
    #pragma unroll
    for (int it = 0; it < 4; it++) {
        cp_async16(&Asm[arr[it] * AS_LD + arc[it]],
                   A + (rowBase + arr[it]) * (size_t)lda + arc[it]);
        cp_async16(&Bsm[brr[it] * BS_LD + brc[it]],
                   B + (size_t)brr[it] * N + colBase + brc[it]);
    }
    cp_commit();

    for (int kb = 0; kb < nk; kb++) {
        int cur = kb & 1;
        int nxt = cur ^ 1;
        if (kb + 1 < nk) {
            int k0 = (kb + 1) * BK;
            #pragma unroll
            for (int it = 0; it < 4; it++) {
                cp_async16(&Asm[nxt * A_BUF + arr[it] * AS_LD + arc[it]],
                           A + (rowBase + arr[it]) * (size_t)lda + k0 + arc[it]);
                cp_async16(&Bsm[nxt * B_BUF + brr[it] * BS_LD + brc[it]],
                           B + (size_t)(k0 + brr[it]) * N + colBase + brc[it]);
            }
            cp_commit();
            cp_wait<1>();                // current stage complete
        } else {
            cp_wait<0>();
        }
        __syncthreads();

        const float* Ab = Asm + cur * A_BUF;
        const float* Bb = Bsm + cur * B_BUF;
        #pragma unroll
        for (int kk = 0; kk < BK; kk += 8) {
            wmma::fragment<wmma::matrix_a, 16, 16, 8, wmma::precision::tf32, wmma::row_major> af[4];
            wmma::fragment<wmma::matrix_b, 16, 16, 8, wmma::precision::tf32, wmma::row_major> bf[2];
            #pragma unroll
            for (int i = 0; i < 4; i++) {
                wmma::load_matrix_sync(af[i], Ab + (wr * 64 + i * 16) * AS_LD + kk, AS_LD);
                #pragma unroll
                for (int e = 0; e < af[i].num_elements; e++)
                    af[i].x[e] = wmma::__float_to_tf32(af[i].x[e]);
            }
            #pragma unroll
            for (int j = 0; j < 2; j++) {
                wmma::load_matrix_sync(bf[j], Bb + kk * BS_LD + wc * 32 + j * 16, BS_LD);
                #pragma unroll
                for (int e = 0; e < bf[j].num_elements; e++)
                    bf[j].x[e] = wmma::__float_to_tf32(bf[j].x[e]);
            }
            #pragma unroll
            for (int i = 0; i < 4; i++)
                #pragma unroll
                for (int j = 0; j < 2; j++)
                    wmma::mma_sync(acc[i][j], af[i], bf[j], acc[i][j]);
        }
        __syncthreads();                 // safe to overwrite buf 'cur' two iters later
    }

    #pragma unroll
    for (int i = 0; i < 4; i++)
        #pragma unroll
        for (int j = 0; j < 2; j++) {
            float* Cp = C + (rowBase + wr * 64 + i * 16) * (size_t)N + colBase + wc * 32 + j * 16;
            wmma::store_matrix_sync(Cp, acc[i][j], N, wmma::mem_row_major);
        }
}

// ---------------- GAT attention scores ----------------
__global__ void attn_scores(const float* __restrict__ aS, const float* __restrict__ aD) {
    int gt = blockIdx.x * blockDim.x + threadIdx.x;
    int w = gt >> 5, lane = gt & 31;
    if (w >= TNT) return;
    const float* xr = g_xp + (size_t)w * HID;
    float s[4], d[4];
    #pragma unroll
    for (int h = 0; h < 4; h++) {
        float v = xr[h * 32 + lane];
        s[h] = v * aS[h * 32 + lane];
        d[h] = v * aD[h * 32 + lane];
    }
    #pragma unroll
    for (int h = 0; h < 4; h++) { s[h] = wsum(s[h]); d[h] = wsum(d[h]); }
    if (lane == 0) {
        *(float4*)&g_asrc[(size_t)w * 4] = make_float4(s[0], s[1], s[2], s[3]);
        *(float4*)&g_adst[(size_t)w * 4] = make_float4(d[0], d[1], d[2], d[3]);
    }
}

// ---------------- per-(t,node) segment softmax (warp per node) ----------------
__global__ void gat_softmax() {
    int gt = blockIdx.x * blockDim.x + threadIdx.x;
    int w = gt >> 5, lane = gt & 31;
    if (w >= TNT) return;
    int t = w / NN, n = w - t * NN;
    int rs = g_rowptr[n], re = g_rowptr[n + 1];
    float* ab = g_alpha + (size_t)t * EPRIME * 4;
    const float* asb = g_asrc + (size_t)t * NN * 4;
    float4 ad = *(const float4*)&g_adst[(size_t)w * 4];

    float m0 = -1e30f, m1 = -1e30f, m2 = -1e30f, m3 = -1e30f;
    for (int i = rs + lane; i < re; i += 32) {
        int s = g_csrsrc[i];
        float4 as = *(const float4*)&asb[(size_t)s * 4];
        float e0 = lrelu(as.x + ad.x);
        float e1 = lrelu(as.y + ad.y);
        float e2 = lrelu(as.z + ad.z);
        float e3 = lrelu(as.w + ad.w);
        *(float4*)&ab[(size_t)i * 4] = make_float4(e0, e1, e2, e3);
        m0 = fmaxf(m0, e0); m1 = fmaxf(m1, e1); m2 = fmaxf(m2, e2); m3 = fmaxf(m3, e3);
    }
    m0 = wmax(m0); m1 = wmax(m1); m2 = wmax(m2); m3 = wmax(m3);
    float s0 = 0.f, s1 = 0.f, s2 = 0.f, s3 = 0.f;
    for (int i = rs + lane; i < re; i += 32) {
        float4 e = *(const float4*)&ab[(size_t)i * 4];
        e.x = __expf(e.x - m0); e.y = __expf(e.y - m1);
        e.z = __expf(e.z - m2); e.w = __expf(e.w - m3);
        *(float4*)&ab[(size_t)i * 4] = e;
        s0 += e.x; s1 += e.y; s2 += e.z; s3 += e.w;
    }
    s0 = wsum(s0); s1 = wsum(s1); s2 = wsum(s2); s3 = wsum(s3);
    if (lane == 0)
        *(float4*)&g_rinv[(size_t)w * 4] = make_float4(
            1.f / (s0 + 1e-16f), 1.f / (s1 + 1e-16f),
            1.f / (s2 + 1e-16f), 1.f / (s3 + 1e-16f));
}

// ---------------- aggregate + bias + residual + LayerNorm + ReLU ----------------
__global__ void gat_aggregate(const float* __restrict__ gb, const float* __restrict__ lg,
                              const float* __restrict__ lb) {
    int gt = blockIdx.x * blockDim.x + threadIdx.x;
    int w = gt >> 5, lane = gt & 31;
    if (w >= TNT) return;
    int t = w / NN, n = w - t * NN;
    int rs = g_rowptr[n], re = g_rowptr[n + 1];
    const float* ab = g_alpha + (size_t)t * EPRIME * 4;
    const float* xb = g_xp + (size_t)t * NN * HID;

    float a0 = 0.f, a1 = 0.f, a2 = 0.f, a3 = 0.f;
    for (int i = rs; i < re; i++) {
        int s = g_csrsrc[i];
        float4 al = *(const float4*)&ab[(size_t)i * 4];
        const float* xr = xb + (size_t)s * HID;
        a0 = fmaf(al.x, xr[lane], a0);
        a1 = fmaf(al.y, xr[32 + lane], a1);
        a2 = fmaf(al.z, xr[64 + lane], a2);
        a3 = fmaf(al.w, xr[96 + lane], a3);
    }
    float4 rv = *(const float4*)&g_rinv[(size_t)w * 4];
    float* hr = g_h + (size_t)w * HID;
    float o0 = a0 * rv.x + gb[lane]      + hr[lane];
    float o1 = a1 * rv.y + gb[32 + lane] + hr[32 + lane];
    float o2 = a2 * rv.z + gb[64 + lane] + hr[64 + lane];
    float o3 = a3 * rv.w + gb[96 + lane] + hr[96 + lane];
    float mu = wsum(o0 + o1 + o2 + o3) * (1.f / 128.f);
    float d0 = o0 - mu, d1 = o1 - mu, d2 = o2 - mu, d3 = o3 - mu;
    float var = wsum(d0 * d0 + d1 * d1 + d2 * d2 + d3 * d3) * (1.f / 128.f);
    float rstd = rsqrtf(var + 1e-5f);
    hr[lane]       = fmaxf(lg[lane]       * d0 * rstd + lb[lane],       0.f);
    hr[32 + lane]  = fmaxf(lg[32 + lane]  * d1 * rstd + lb[32 + lane],  0.f);
    hr[64 + lane]  = fmaxf(lg[64 + lane]  * d2 * rstd + lb[64 + lane],  0.f);
    hr[96 + lane]  = fmaxf(lg[96 + lane]  * d3 * rstd + lb[96 + lane],  0.f);
}

// ---------------- LSTM gates ----------------
__global__ void lstm_gates(const float* __restrict__ zx, const float* __restrict__ zh,
                           const float* __restrict__ bih, const float* __restrict__ bhh,
                           float* __restrict__ c, float* __restrict__ hout) {
    int idx = blockIdx.x * blockDim.x + threadIdx.x;
    if (idx >= NN * HID) return;
    int n = idx >> 7, j = idx & 127;
    const float* zr = zx + (size_t)n * 512;
    float zi = zr[j], zf = zr[128 + j], zg = zr[256 + j], zo = zr[384 + j];
    if (zh) {
        const float* hr2 = zh + (size_t)n * 512;
        zi += hr2[j]; zf += hr2[128 + j]; zg += hr2[256 + j]; zo += hr2[384 + j];
    }
    zi += bih[j]       + bhh[j];
    zf += bih[128 + j] + bhh[128 + j];
    zg += bih[256 + j] + bhh[256 + j];
    zo += bih[384 + j] + bhh[384 + j];
    float ig = 1.f / (1.f + __expf(-zi));
    float fg = 1.f / (1.f + __expf(-zf));
    float gg = tanhf(zg);
    float og = 1.f / (1.f + __expf(-zo));
    float cn = fg * c[idx] + ig * gg;
    c[idx] = cn;
    hout[(size_t)n * 256 + j] = og * tanhf(cn);
}

// ---------------- output head ----------------
__global__ void head_kernel(const float* __restrict__ W1, const float* __restrict__ b1,
                            const float* __restrict__ W2, const float* __restrict__ b2,
                            float* __restrict__ out) {
    __shared__ float hrow[128];
    __shared__ float part[2];
    int n = blockIdx.x;
    int j = threadIdx.x;  // 64
    const float* hr = g_hcat + (size_t)n * 256 + 128;   // h1
    hrow[j] = hr[j];
    hrow[j + 64] = hr[j + 64];
    __syncthreads();
    float acc = b1[j];
    #pragma unroll
    for (int k = 0; k < 128; k++) acc = fmaf(hrow[k], W1[k * 64 + j], acc);
    float v = fmaxf(acc, 0.f) * W2[j];
    v = wsum(v);
    if ((j & 31) == 0) part[j >> 5] = v;
    __syncthreads();
    if (j == 0) out[n] = part[0] + part[1] + b2[0];
}

// ---------------- host launch ----------------
static float* symf(const void* s) { void* p = nullptr; cudaGetSymbolAddress(&p, s); return (float*)p; }

extern "C" void kernel_launch(void* const* d_in, const int* in_sizes, int n_in,
                              void* d_out, int out_size) {
    const float* xs    = (const float*)d_in[0];
    const float* xd    = (const float*)d_in[1];
    const int*   ei    = (const int*)  d_in[2];
    const float* projW = (const float*)d_in[3];
    const float* projb = (const float*)d_in[4];
    const float* gatW  = (const float*)d_in[5];
    const float* attS  = (const float*)d_in[6];
    const float* attD  = (const float*)d_in[7];
    const float* gatb  = (const float*)d_in[8];
    const float* lng   = (const float*)d_in[9];
    const float* lnb   = (const float*)d_in[10];
    const float* Wih0  = (const float*)d_in[11];
    const float* Whh0  = (const float*)d_in[12];
    const float* bih0  = (const float*)d_in[13];
    const float* bhh0  = (const float*)d_in[14];
    const float* Wih1  = (const float*)d_in[15];
    const float* Whh1  = (const float*)d_in[16];
    const float* bih1  = (const float*)d_in[17];
    const float* bhh1  = (const float*)d_in[18];
    const float* oW1   = (const float*)d_in[19];
    const float* ob1   = (const float*)d_in[20];
    const float* oW2   = (const float*)d_in[21];
    const float* ob2   = (const float*)d_in[22];
    float* out = (float*)d_out;

    float* p_h     = symf(g_h);
    float* p_xp    = symf(g_xp);
    float* p_WihT0 = symf(g_WihT0);
    float* p_WhhT0 = symf(g_WhhT0);
    float* p_zx0   = symf(g_zx0);
    float* p_zh    = symf(g_zh);
    float* p_z1    = symf(g_z1);
    float* p_hcat  = symf(g_hcat);
    float* p_c0    = symf(g_c0);
    float* p_c1    = symf(g_c1);
    float* p_deg   = symf(g_deg);
    float* p_Wcat1 = symf(g_Wcat1);

    // allow 75.8 KB dynamic smem for the double-buffered GEMM (idempotent)
    cudaFuncSetAttribute(sgemm_tc, cudaFuncAttributeMaxDynamicSharedMemorySize,
                         GEMM_SMEM_BYTES);

    // --- CSR build ---
    cudaMemsetAsync(p_deg, 0, NN * sizeof(int));
    hist_dst<<<(EE + 255) / 256, 256>>>(ei + EE);
    scan_rowptr<<<1, 1024>>>();
    init_cursor_selfloop<<<(NN + 255) / 256, 256>>>();
    scatter_edges<<<(EE + 255) / 256, 256>>>(ei, ei + EE);

    // --- LSTM weight prep: keep [K,N] row-major for matrix_b ---
    const int TB = (512 * 128 + 255) / 256;
    transp_512x128<<<TB, 256>>>(Wih0, p_WihT0);
    transp_512x128<<<TB, 256>>>(Whh0, p_WhhT0);
    build_wcat1<<<TB, 256>>>(Wih1, Whh1);

    // --- zero LSTM state (hcat pad rows must stay 0 for padded GEMM rows) ---
    cudaMemsetAsync(p_hcat, 0, (size_t)NNP * 256 * sizeof(float));
    cudaMemsetAsync(p_c0,   0, (size_t)NN * HID * sizeof(float));
    cudaMemsetAsync(p_c1,   0, (size_t)NN * HID * sizeof(float));

    // --- GNN phase, batched over all T timesteps ---
    proj_kernel<<<TNT, 128>>>(xs, xd, projW, projb);

    const int WBLK = (TNT * 32 + 255) / 256;
    for (int l = 0; l < 3; l++) {
        sgemm_tc<<<dim3(1, TNT / 128), 256, GEMM_SMEM_BYTES>>>(
            p_h, HID, gatW + (size_t)l * HID * HID, p_xp, HID, HID);
        attn_scores<<<WBLK, 256>>>(attS + l * 128, attD + l * 128);
        gat_softmax<<<WBLK, 256>>>();
        gat_aggregate<<<WBLK, 256>>>(gatb + l * 128, lng + l * 128, lnb + l * 128);
    }

    // --- precompute x@Wih0^T for all timesteps in one big GEMM ---
    sgemm_tc<<<dim3(4, TNT / 128), 256, GEMM_SMEM_BYTES>>>(p_h, HID, p_WihT0, p_zx0, 512, HID);

    // --- sequential LSTM over T ---
    const dim3 gemmNN(4, NNP / 128);
    const int GBLK = (NN * HID + 255) / 256;
    for (int t = 0; t < TT; t++) {
        sgemm_tc<<<gemmNN, 256, GEMM_SMEM_BYTES>>>(p_hcat, 256, p_WhhT0, p_zh, 512, HID);
        lstm_gates<<<GBLK, 256>>>(p_zx0 + (size_t)t * NN * 512, p_zh, bih0, bhh0, p_c0, p_hcat);
        sgemm_tc<<<gemmNN, 256, GEMM_SMEM_BYTES>>>(p_hcat, 256, p_Wcat1, p_z1, 512, 256);
        lstm_gates<<<GBLK, 256>>>(p_z1, nullptr, bih1, bhh1, p_c1, p_hcat + 128);
    }

    // --- output head ---
    head_kernel<<<NN, 64>>>(oW1, ob1, oW2, ob2, out);
}